// round 5
// baseline (speedup 1.0000x reference)
#include <cuda_runtime.h>

#define BATCH 16
#define CHN   8
#define HH    512
#define WW    512
#define TW    128   // tile width (pixels)
#define TH    8     // tile height (rows)
#define TILES_X (WW / TW)   // 4
#define TILES_Y (HH / TH)   // 64
#define NBLK (TILES_X * TILES_Y * BATCH)  // 4096

#define EPR   132                    // pair-entries per row (pitch); 8B each
#define ROWB  (EPR * 8)              // 1056 bytes per row (66*16 -> 16B aligned)
#define NROWS (TH + 2)               // 10
#define SMEM_PAIR (CHN * NROWS * ROWB)   // 84480 bytes

// Scratch (device globals: allocation-free rule)
__device__ float g_y[BATCH * CHN * HH * WW];     // conv output (134 MB)
__device__ float g_part[NBLK * 16];              // per-block [sum[8], sumsq[8]]
__device__ float g_scale[CHN];
__device__ float g_shift[CHN];

// ---------- f32x2 helpers ----------
__device__ __forceinline__ void fma2(unsigned long long& d, unsigned long long a,
                                     unsigned long long b) {
    asm("fma.rn.f32x2 %0, %1, %2, %0;" : "+l"(d) : "l"(a), "l"(b));
}
__device__ __forceinline__ void add2(unsigned long long& d, unsigned long long a) {
    asm("add.rn.f32x2 %0, %0, %1;" : "+l"(d) : "l"(a));
}
__device__ __forceinline__ float2 up2(unsigned long long v) {
    float2 f;
    asm("mov.b64 {%0, %1}, %2;" : "=f"(f.x), "=f"(f.y) : "l"(v));
    return f;
}
__device__ __forceinline__ int swz(int e) {
    return e ^ (((e >> 4) & 7) << 1);
}

// ---------- Kernel 1: conv3x3 + bias -> g_y, per-block channel sum/sumsq ----------
// 128 threads: tx (8 groups of 16 contiguous px) x cz (2 cout-halves) x ty (8 rows)
// Smem holds a PAIR-DUPLICATED tile: entry e = (pad[e], pad[e+1]), XOR-swizzled.
__global__ __launch_bounds__(128, 2) void conv_kernel(
    const float* __restrict__ x, const float* __restrict__ lin_w,
    const float* __restrict__ lin_b) {
    extern __shared__ char smem[];                      // pair tile, 84480 B
    __shared__ float2 s_w[CHN * 9 * 8];                 // duplicated (w,w): 4608 B
    __shared__ float2 s_bias[8];

    const int tid = threadIdx.x;
    const int tx = tid & 7;            // 16-px group
    const int cz = (tid >> 3) & 1;     // cout half
    const int ty = tid >> 4;           // row
    const int bw = blockIdx.x, bh = blockIdx.y, b = blockIdx.z;
    const int col0 = bw * TW, row0 = bh * TH;

    // Weights: s_w[(cin*9 + kh*3+kw)*8 + cout] = (w, w)
    for (int i = tid; i < CHN * 9 * 8; i += 128) {
        int cout = i & 7;
        int t = (i >> 3) % 9;
        int cin = i / 72;
        float w = lin_w[(cin * 8 + cout) * 9 + t];
        s_w[i] = make_float2(w, w);
    }
    if (tid < 8) {
        float bs = 0.f;
        #pragma unroll
        for (int cin = 0; cin < 8; cin++) bs += lin_b[cin * 8 + tid];
        s_bias[tid] = make_float2(bs, bs);
    }

    // Stage pair tile. pad[k] = x[row, col0 + k - 1]; entry e = (pad[e], pad[e+1]),
    // e in [0, 130). Written at swizzled position.
    for (int i = tid; i < CHN * NROWS * 130; i += 128) {
        int e = i % 130;
        int t = i / 130;
        int sr = t % NROWS;
        int c = t / NROWS;
        int gr = row0 + sr - 1;
        int gc0 = col0 + e - 1;
        float v0 = 0.f, v1 = 0.f;
        if ((unsigned)gr < HH) {
            const float* rp = x + ((b * CHN + c) * HH + gr) * WW;
            if ((unsigned)gc0 < WW) v0 = rp[gc0];
            if ((unsigned)(gc0 + 1) < WW) v1 = rp[gc0 + 1];
        }
        *(float2*)(smem + (c * NROWS + sr) * ROWB + swz(e) * 8) = make_float2(v0, v1);
    }
    __syncthreads();

    // Accumulators: 4 couts x 8 pixel-pairs (16 px), init = bias
    const int coBase = cz * 4;
    unsigned long long acc[4][8];
    #pragma unroll
    for (int j = 0; j < 4; j++) {
        unsigned long long bz = ((const unsigned long long*)s_bias)[coBase + j];
        #pragma unroll
        for (int p = 0; p < 8; p++) acc[j][p] = bz;
    }

    // 9 persistent row pointers (swizzled entry offsets for e = 16*tx + 2q)
    const char* p[9];
    #pragma unroll
    for (int q = 0; q < 9; q++) {
        int e = 16 * tx + 2 * q;
        p[q] = smem + ty * ROWB + swz(e) * 8;
    }

    const unsigned long long* __restrict__ swp = (const unsigned long long*)s_w;

    #pragma unroll 1
    for (int cin = 0; cin < 8; cin++) {
        #pragma unroll
        for (int kh = 0; kh < 3; kh++) {
            // L[q] = (P[16tx+2q], P[16tx+2q+1]) : even + odd pairs, no MOVs
            ulonglong2 L[9];
            #pragma unroll
            for (int q = 0; q < 9; q++)
                L[q] = *(const ulonglong2*)(p[q] + kh * ROWB);

            const unsigned long long* wrow = swp + (cin * 9 + kh * 3) * 8;
            #pragma unroll
            for (int j = 0; j < 4; j++) {
                const int co = coBase + j;
                unsigned long long wA = wrow[co];
                unsigned long long wB = wrow[8 + co];
                unsigned long long wC = wrow[16 + co];
                #pragma unroll
                for (int m = 0; m < 8; m++) {
                    fma2(acc[j][m], L[m].x, wA);       // tap kw=0 (P[2m])
                    fma2(acc[j][m], L[m].y, wB);       // tap kw=1 (P[2m+1])
                    fma2(acc[j][m], L[m + 1].x, wC);   // tap kw=2 (P[2m+2])
                }
            }
        }
        #pragma unroll
        for (int q = 0; q < 9; q++) p[q] += NROWS * ROWB;   // next channel
    }

    // Store y + thread-local channel sums
    const int orow = row0 + ty;
    const int scb = tx * 16;
    float vals[16];
    #pragma unroll
    for (int v = 0; v < 16; v++) vals[v] = 0.f;
    #pragma unroll
    for (int j = 0; j < 4; j++) {
        const int co = coBase + j;
        int off = ((b * 8 + co) * HH + orow) * WW + col0 + scb;
        *(ulonglong2*)(g_y + off)      = make_ulonglong2(acc[j][0], acc[j][1]);
        *(ulonglong2*)(g_y + off + 4)  = make_ulonglong2(acc[j][2], acc[j][3]);
        *(ulonglong2*)(g_y + off + 8)  = make_ulonglong2(acc[j][4], acc[j][5]);
        *(ulonglong2*)(g_y + off + 12) = make_ulonglong2(acc[j][6], acc[j][7]);
        unsigned long long ss = 0ull, sq = 0ull;
        #pragma unroll
        for (int pp = 0; pp < 8; pp++) {
            add2(ss, acc[j][pp]);
            fma2(sq, acc[j][pp], acc[j][pp]);
        }
        float2 fs = up2(ss), fq = up2(sq);
        vals[co] = fs.x + fs.y;
        vals[8 + co] = fq.x + fq.y;
    }

    // Warp reduce (4 warps of 32)
    #pragma unroll
    for (int v = 0; v < 16; v++) {
        float t = vals[v];
        #pragma unroll
        for (int o = 16; o > 0; o >>= 1) t += __shfl_xor_sync(0xFFFFFFFFu, t, o);
        vals[v] = t;
    }
    __syncthreads();  // done with pair tile; reuse as reduction scratch
    float* sred = (float*)smem;  // 4 warps * 16
    int wid = tid >> 5, lane = tid & 31;
    if (lane == 0) {
        #pragma unroll
        for (int v = 0; v < 16; v++) sred[wid * 16 + v] = vals[v];
    }
    __syncthreads();
    if (tid < 16) {
        float t = sred[tid] + sred[16 + tid] + sred[32 + tid] + sred[48 + tid];
        int blin = (b * gridDim.y + bh) * gridDim.x + bw;
        g_part[blin * 16 + tid] = t;
    }
}

// ---------- Kernel 2: finalize statistics ----------
__global__ __launch_bounds__(1024) void stats_kernel(const float* __restrict__ gamma,
                                                     const float* __restrict__ beta) {
    __shared__ float red[1024];
    int tid = threadIdx.x;
    int v = tid & 15, g = tid >> 4;   // 64 groups
    float s = 0.f;
    for (int i = g; i < NBLK; i += 64) s += g_part[i * 16 + v];
    red[tid] = s;
    __syncthreads();
    float tot = 0.f;
    if (tid < 16) {
        #pragma unroll
        for (int gg = 0; gg < 64; gg++) tot += red[gg * 16 + tid];
    }
    __syncthreads();
    if (tid < 16) red[tid] = tot;
    __syncthreads();
    if (tid < 8) {
        const float n = (float)(BATCH * HH * WW);
        float mean = red[tid] / n;
        float var = red[tid + 8] / n - mean * mean;
        float sc = gamma[tid] * rsqrtf(var + 1e-5f);
        g_scale[tid] = sc;
        g_shift[tid] = beta[tid] - mean * sc;
    }
}

// ---------- Kernel 3: normalize + ReLU ----------
__global__ __launch_bounds__(256) void norm_kernel(float* __restrict__ out) {
    __shared__ float ssc[8], ssh[8];
    if (threadIdx.x < 8) {
        ssc[threadIdx.x] = g_scale[threadIdx.x];
        ssh[threadIdx.x] = g_shift[threadIdx.x];
    }
    __syncthreads();
    int i = blockIdx.x * 256 + threadIdx.x;           // float4 index
    int c = (i >> 16) & 7;                            // 65536 float4 per channel
    float4 v = ((const float4*)g_y)[i];
    float s = ssc[c], h = ssh[c];
    v.x = fmaxf(fmaf(v.x, s, h), 0.f);
    v.y = fmaxf(fmaf(v.y, s, h), 0.f);
    v.z = fmaxf(fmaf(v.z, s, h), 0.f);
    v.w = fmaxf(fmaf(v.w, s, h), 0.f);
    ((float4*)out)[i] = v;
}

extern "C" void kernel_launch(void* const* d_in, const int* in_sizes, int n_in,
                              void* d_out, int out_size) {
    const float* x     = (const float*)d_in[0];
    const float* lin_w = (const float*)d_in[1];
    const float* lin_b = (const float*)d_in[2];
    const float* gamma = (const float*)d_in[3];
    const float* beta  = (const float*)d_in[4];
    float* out = (float*)d_out;

    static int attr_done = 0;
    if (!attr_done) {
        cudaFuncSetAttribute(conv_kernel,
                             cudaFuncAttributeMaxDynamicSharedMemorySize, SMEM_PAIR);
        attr_done = 1;
    }

    dim3 grid(TILES_X, TILES_Y, BATCH);
    conv_kernel<<<grid, 128, SMEM_PAIR>>>(x, lin_w, lin_b);
    stats_kernel<<<1, 1024>>>(gamma, beta);
    int n4 = BATCH * CHN * HH * WW / 4;   // 8388608
    norm_kernel<<<n4 / 256, 256>>>(out);
}

// round 7
// speedup vs baseline: 3.1076x; 3.1076x over previous
#include <cuda_runtime.h>

#define BATCH 16
#define CHN   8
#define HH    512
#define WW    512
#define TW    128
#define TH    8
#define TILES_X (WW / TW)   // 4
#define TILES_Y (HH / TH)   // 64
#define NBLK (TILES_X * TILES_Y * BATCH)  // 4096

#define EPR    136                  // pair entries per row (8B each) -> 1088B pitch
#define ROWB   (EPR * 8)            // 1088
#define NROWS  (TH + 2)             // 10
#define CSTRIDE (NROWS * ROWB)      // 10880
#define SMEM_DYN (4 * CSTRIDE)      // 43520 bytes (4 channels staged per phase)

// Scratch (device globals: allocation-free rule)
__device__ float g_y[BATCH * CHN * HH * WW];
__device__ float g_part[NBLK * 16];
__device__ float g_scale[CHN];
__device__ float g_shift[CHN];

// ---------- helpers ----------
__device__ __forceinline__ void fma2(unsigned long long& d, unsigned long long a,
                                     unsigned long long b) {
    asm("fma.rn.f32x2 %0, %1, %2, %0;" : "+l"(d) : "l"(a), "l"(b));
}
__device__ __forceinline__ void add2(unsigned long long& d, unsigned long long a) {
    asm("add.rn.f32x2 %0, %0, %1;" : "+l"(d) : "l"(a));
}
__device__ __forceinline__ float2 up2(unsigned long long v) {
    float2 f;
    asm("mov.b64 {%0, %1}, %2;" : "=f"(f.x), "=f"(f.y) : "l"(v));
    return f;
}
__device__ __forceinline__ int swz(int e) {           // XOR swizzle on pair-entry index
    return e ^ (((e >> 4) & 7) << 1);
}
__device__ __forceinline__ void stpair(unsigned addr, float a, float b) {
    asm volatile("st.shared.v2.f32 [%0], {%1, %2};" :: "r"(addr), "f"(a), "f"(b));
}
#define LDS128I(lo, hi, addr, IMM) \
    asm("ld.shared.v2.u64 {%0, %1}, [%2+" IMM "];" : "=l"(lo), "=l"(hi) : "r"(addr))

// taps: 8 couts x (3 taps x 4 pairs) per (cin,kh)
__device__ __forceinline__ void taps(unsigned long long acc[8][4],
                                     const ulonglong2 L[5],
                                     const unsigned long long* __restrict__ wrow) {
    #pragma unroll
    for (int co = 0; co < 8; co++) {
        unsigned long long wA = wrow[co];
        unsigned long long wB = wrow[8 + co];
        unsigned long long wC = wrow[16 + co];
        #pragma unroll
        for (int m = 0; m < 4; m++) {
            fma2(acc[co][m], L[m].x, wA);
            fma2(acc[co][m], L[m].y, wB);
            fma2(acc[co][m], L[m + 1].x, wC);
        }
    }
}

// ---------- Kernel 1: conv3x3 + bias -> g_y, per-block channel sum/sumsq ----------
__global__ __launch_bounds__(128, 4) void conv_kernel(
    const float* __restrict__ x, const float* __restrict__ lin_w,
    const float* __restrict__ lin_b) {
    extern __shared__ char smem[];                    // 43520 B pair tile (4 channels)
    __shared__ float2 s_w[CHN * 9 * 8];               // (w,w) pairs: 4608 B
    __shared__ float2 s_bias[8];

    const int tid = threadIdx.x;
    const int tx = tid & 15;          // 8-px group
    const int ty = tid >> 4;          // row 0..7
    const int bw = blockIdx.x, bh = blockIdx.y, b = blockIdx.z;
    const int col0 = bw * TW, row0 = bh * TH;
    const unsigned sbase = (unsigned)__cvta_generic_to_shared(smem);

    // Weights: s_w[(cin*9 + tap)*8 + cout] = (w, w)
    for (int i = tid; i < CHN * 9 * 8; i += 128) {
        int cout = i & 7;
        int t = (i >> 3) % 9;
        int cin = i / 72;
        float w = lin_w[(cin * 8 + cout) * 9 + t];
        s_w[i] = make_float2(w, w);
    }
    if (tid < 8) {
        float bs = 0.f;
        #pragma unroll
        for (int cin = 0; cin < 8; cin++) bs += lin_b[cin * 8 + tid];
        s_bias[tid] = make_float2(bs, bs);
    }

    // Accumulators (persist across both phases), init = bias
    unsigned long long acc[8][4];

    // Thread's 5 LDS.128 base offsets (row ty, channel slot 0)
    unsigned off0, off1, off2, off3, off4;
    {
        int e0 = 8 * tx;
        off0 = sbase + ty * ROWB + swz(e0 + 0) * 8;
        off1 = sbase + ty * ROWB + swz(e0 + 2) * 8;
        off2 = sbase + ty * ROWB + swz(e0 + 4) * 8;
        off3 = sbase + ty * ROWB + swz(e0 + 6) * 8;
        off4 = sbase + ty * ROWB + swz(e0 + 8) * 8;
    }
    const unsigned long long* __restrict__ swp = (const unsigned long long*)s_w;

    #pragma unroll 1
    for (int phase = 0; phase < 2; phase++) {
        const int cbase = phase * 4;
        // ---- stage 4 channels (pair-duplicated, swizzled) ----
        const float* xb = x + ((size_t)(b * CHN + cbase)) * HH * WW;
        for (int i = tid; i < 1280; i += 128) {        // 40 (ch,row) x 32 chunks
            int chunk = i & 31;
            int t = i >> 5;            // 0..39
            int r = t % 10;
            int c = t / 10;            // channel slot 0..3
            int gr = row0 + r - 1;
            bool rok = (unsigned)gr < HH;
            const float* rp = xb + c * (HH * WW) + gr * WW;
            int gc = col0 + chunk * 4;                 // cols gc..gc+4 used
            float4 A = make_float4(0.f, 0.f, 0.f, 0.f);
            float b0 = 0.f;
            if (rok) {
                A = *(const float4*)(rp + gc);
                if (gc + 4 < WW) b0 = rp[gc + 4];
            }
            unsigned ra = sbase + c * CSTRIDE + r * ROWB;
            int e = chunk * 4 + 1;
            stpair(ra + swz(e) * 8,     A.x, A.y);
            stpair(ra + swz(e + 1) * 8, A.y, A.z);
            stpair(ra + swz(e + 2) * 8, A.z, A.w);
            stpair(ra + swz(e + 3) * 8, A.w, b0);
        }
        if (tid < 80) {                                // edge entries e=0 and e=129
            int side = tid & 1;
            int t = tid >> 1;          // 0..39
            int r = t % 10;
            int c = t / 10;
            int gr = row0 + r - 1;
            bool rok = (unsigned)gr < HH;
            const float* rp = xb + c * (HH * WW) + gr * WW;
            unsigned ra = sbase + c * CSTRIDE + r * ROWB;
            if (!side) {
                float v0 = (rok && col0 >= 1) ? rp[col0 - 1] : 0.f;
                float v1 = rok ? rp[col0] : 0.f;
                stpair(ra + swz(0) * 8, v0, v1);
            } else {
                float v0 = (rok && col0 + 128 < WW) ? rp[col0 + 128] : 0.f;
                stpair(ra + swz(129) * 8, v0, 0.f);
            }
        }
        __syncthreads();

        if (phase == 0) {
            #pragma unroll
            for (int co = 0; co < 8; co++) {
                unsigned long long bz = ((const unsigned long long*)s_bias)[co];
                #pragma unroll
                for (int m = 0; m < 4; m++) acc[co][m] = bz;
            }
        }

        // ---- compute 4 channels ----
        unsigned o0 = off0, o1 = off1, o2 = off2, o3 = off3, o4 = off4;
        #pragma unroll
        for (int s = 0; s < 4; s++) {
            const int cin = cbase + s;
            {   // kh = 0
                ulonglong2 L[5];
                LDS128I(L[0].x, L[0].y, o0, "0");
                LDS128I(L[1].x, L[1].y, o1, "0");
                LDS128I(L[2].x, L[2].y, o2, "0");
                LDS128I(L[3].x, L[3].y, o3, "0");
                LDS128I(L[4].x, L[4].y, o4, "0");
                taps(acc, L, swp + (cin * 9 + 0) * 8);
            }
            {   // kh = 1
                ulonglong2 L[5];
                LDS128I(L[0].x, L[0].y, o0, "1088");
                LDS128I(L[1].x, L[1].y, o1, "1088");
                LDS128I(L[2].x, L[2].y, o2, "1088");
                LDS128I(L[3].x, L[3].y, o3, "1088");
                LDS128I(L[4].x, L[4].y, o4, "1088");
                taps(acc, L, swp + (cin * 9 + 3) * 8);
            }
            {   // kh = 2
                ulonglong2 L[5];
                LDS128I(L[0].x, L[0].y, o0, "2176");
                LDS128I(L[1].x, L[1].y, o1, "2176");
                LDS128I(L[2].x, L[2].y, o2, "2176");
                LDS128I(L[3].x, L[3].y, o3, "2176");
                LDS128I(L[4].x, L[4].y, o4, "2176");
                taps(acc, L, swp + (cin * 9 + 6) * 8);
            }
            o0 += CSTRIDE; o1 += CSTRIDE; o2 += CSTRIDE; o3 += CSTRIDE; o4 += CSTRIDE;
        }
        __syncthreads();   // tile free before restage / reduction reuse
    }

    // ---- store y + channel sums ----
    const int orow = row0 + ty;
    float vals[16];
    #pragma unroll
    for (int co = 0; co < 8; co++) {
        size_t off = ((size_t)(b * 8 + co) * HH + orow) * WW + col0 + 8 * tx;
        *(ulonglong2*)(g_y + off)     = make_ulonglong2(acc[co][0], acc[co][1]);
        *(ulonglong2*)(g_y + off + 4) = make_ulonglong2(acc[co][2], acc[co][3]);
        unsigned long long ss = 0ull, sq = 0ull;
        #pragma unroll
        for (int m = 0; m < 4; m++) {
            add2(ss, acc[co][m]);
            fma2(sq, acc[co][m], acc[co][m]);
        }
        float2 fs = up2(ss), fq = up2(sq);
        vals[co] = fs.x + fs.y;
        vals[8 + co] = fq.x + fq.y;
    }
    #pragma unroll
    for (int v = 0; v < 16; v++) {
        float t = vals[v];
        #pragma unroll
        for (int o = 16; o > 0; o >>= 1) t += __shfl_xor_sync(0xFFFFFFFFu, t, o);
        vals[v] = t;
    }
    float* sred = (float*)smem;   // tile no longer needed
    int wid = tid >> 5, lane = tid & 31;
    if (lane == 0) {
        #pragma unroll
        for (int v = 0; v < 16; v++) sred[wid * 16 + v] = vals[v];
    }
    __syncthreads();
    if (tid < 16) {
        float t = sred[tid] + sred[16 + tid] + sred[32 + tid] + sred[48 + tid];
        int blin = (b * gridDim.y + bh) * gridDim.x + bw;
        g_part[blin * 16 + tid] = t;
    }
}

// ---------- Kernel 2: finalize statistics ----------
__global__ __launch_bounds__(1024) void stats_kernel(const float* __restrict__ gamma,
                                                     const float* __restrict__ beta) {
    __shared__ float red[1024];
    int tid = threadIdx.x;
    int v = tid & 15, g = tid >> 4;   // 64 groups
    float s = 0.f;
    for (int i = g; i < NBLK; i += 64) s += g_part[i * 16 + v];
    red[tid] = s;
    __syncthreads();
    float tot = 0.f;
    if (tid < 16) {
        #pragma unroll
        for (int gg = 0; gg < 64; gg++) tot += red[gg * 16 + tid];
    }
    __syncthreads();
    if (tid < 16) red[tid] = tot;
    __syncthreads();
    if (tid < 8) {
        const float n = (float)(BATCH * HH * WW);
        float mean = red[tid] / n;
        float var = red[tid + 8] / n - mean * mean;
        float sc = gamma[tid] * rsqrtf(var + 1e-5f);
        g_scale[tid] = sc;
        g_shift[tid] = beta[tid] - mean * sc;
    }
}

// ---------- Kernel 3: normalize + ReLU ----------
__global__ __launch_bounds__(256) void norm_kernel(float* __restrict__ out) {
    __shared__ float ssc[8], ssh[8];
    if (threadIdx.x < 8) {
        ssc[threadIdx.x] = g_scale[threadIdx.x];
        ssh[threadIdx.x] = g_shift[threadIdx.x];
    }
    __syncthreads();
    int i = blockIdx.x * 256 + threadIdx.x;
    int c = (i >> 16) & 7;
    float4 v = ((const float4*)g_y)[i];
    float s = ssc[c], h = ssh[c];
    v.x = fmaxf(fmaf(v.x, s, h), 0.f);
    v.y = fmaxf(fmaf(v.y, s, h), 0.f);
    v.z = fmaxf(fmaf(v.z, s, h), 0.f);
    v.w = fmaxf(fmaf(v.w, s, h), 0.f);
    ((float4*)out)[i] = v;
}

extern "C" void kernel_launch(void* const* d_in, const int* in_sizes, int n_in,
                              void* d_out, int out_size) {
    const float* x     = (const float*)d_in[0];
    const float* lin_w = (const float*)d_in[1];
    const float* lin_b = (const float*)d_in[2];
    const float* gamma = (const float*)d_in[3];
    const float* beta  = (const float*)d_in[4];
    float* out = (float*)d_out;

    dim3 grid(TILES_X, TILES_Y, BATCH);
    conv_kernel<<<grid, 128, SMEM_DYN>>>(x, lin_w, lin_b);
    stats_kernel<<<1, 1024>>>(gamma, beta);
    int n4 = BATCH * CHN * HH * WW / 4;
    norm_kernel<<<n4 / 256, 256>>>(out);
}